// round 1
// baseline (speedup 1.0000x reference)
#include <cuda_runtime.h>
#include <math.h>

#define NN 100000          // nodes (compile-time, matches reference)

// ---- scratch (allocation-free: __device__ globals) ----
__device__ __align__(256) int   g_deg [NN];
__device__ __align__(256) float g_dinv[NN];
__device__ __align__(256) float g_h1  [NN * 64];
__device__ __align__(256) float g_agg1[NN * 64];
__device__ __align__(256) float g_h2  [NN * 32];
__device__ __align__(256) float g_agg2[NN * 32];

// ---------------------------------------------------------------
// 1) degree = 1 (self loop) + count of incoming edges
// ---------------------------------------------------------------
__global__ void k_init_deg() {
    int i = blockIdx.x * blockDim.x + threadIdx.x;
    if (i < NN) g_deg[i] = 1;
}

__global__ void k_count(const int* __restrict__ dst, int E) {
    int e = blockIdx.x * blockDim.x + threadIdx.x;
    if (e < E) atomicAdd(&g_deg[dst[e]], 1);
}

__global__ void k_dinv() {
    int i = blockIdx.x * blockDim.x + threadIdx.x;
    if (i < NN) g_dinv[i] = 1.0f / sqrtf((float)g_deg[i]);
}

// ---------------------------------------------------------------
// 2) h1 = x @ W1  (N x 7 @ 7 x 64), fused self-loop init:
//    agg1[i] = dinv[i]^2 * h1[i]
// ---------------------------------------------------------------
__global__ void k_h1(const float* __restrict__ x, const float* __restrict__ W1) {
    __shared__ float W[7 * 64];
    for (int t = threadIdx.x; t < 7 * 64; t += blockDim.x) W[t] = W1[t];
    __syncthreads();

    int i = blockIdx.x * blockDim.x + threadIdx.x;
    if (i >= NN) return;

    float xi[7];
#pragma unroll
    for (int k = 0; k < 7; k++) xi[k] = x[i * 7 + k];

    float s = g_dinv[i];
    s = s * s;

#pragma unroll 4
    for (int c4 = 0; c4 < 16; c4++) {
        float acc0 = 0.f, acc1 = 0.f, acc2 = 0.f, acc3 = 0.f;
#pragma unroll
        for (int k = 0; k < 7; k++) {
            const float* wr = &W[k * 64 + c4 * 4];
            acc0 += xi[k] * wr[0];
            acc1 += xi[k] * wr[1];
            acc2 += xi[k] * wr[2];
            acc3 += xi[k] * wr[3];
        }
        *(float4*)&g_h1[i * 64 + c4 * 4]   = make_float4(acc0, acc1, acc2, acc3);
        *(float4*)&g_agg1[i * 64 + c4 * 4] = make_float4(acc0 * s, acc1 * s, acc2 * s, acc3 * s);
    }
}

// ---------------------------------------------------------------
// 3) edge scatter layer 1: agg1[dst] += norm * h1[src]  (64 wide)
//    uses red.global.add.v4.f32 (no-return reduction, 4 floats/op)
// ---------------------------------------------------------------
__device__ __forceinline__ void red_add_v4(float* p, float a, float b, float c, float d) {
    asm volatile("red.global.add.v4.f32 [%0], {%1, %2, %3, %4};"
                 :: "l"(p), "f"(a), "f"(b), "f"(c), "f"(d) : "memory");
}

__global__ void k_edge1(const int* __restrict__ src, const int* __restrict__ dst, int E) {
    int e = blockIdx.x * blockDim.x + threadIdx.x;
    if (e >= E) return;
    int s = src[e], d = dst[e];
    float nrm = g_dinv[s] * g_dinv[d];
    const float4* hs = (const float4*)&g_h1[s * 64];
    float* ad = &g_agg1[d * 64];
#pragma unroll
    for (int q = 0; q < 16; q++) {
        float4 v = hs[q];
        red_add_v4(ad + q * 4, v.x * nrm, v.y * nrm, v.z * nrm, v.w * nrm);
    }
}

// ---------------------------------------------------------------
// 4) h2 = relu(agg1 + b1) @ W2   (64 -> 32), warp per node,
//    fused self-loop init: agg2[i] = dinv[i]^2 * h2[i]
// ---------------------------------------------------------------
__global__ void k_h2(const float* __restrict__ b1, const float* __restrict__ W2) {
    __shared__ float W[64 * 32];
    __shared__ float b[64];
    for (int t = threadIdx.x; t < 64 * 32; t += blockDim.x) W[t] = W2[t];
    if (threadIdx.x < 64) b[threadIdx.x] = b1[threadIdx.x];
    __syncthreads();

    int gwarp = (blockIdx.x * blockDim.x + threadIdx.x) >> 5;
    int lane  = threadIdx.x & 31;
    if (gwarp >= NN) return;

    const float* row = &g_agg1[gwarp * 64];
    float acc = 0.f;
#pragma unroll
    for (int k = 0; k < 64; k++) {
        float a = fmaxf(row[k] + b[k], 0.f);   // broadcast load within warp
        acc += a * W[k * 32 + lane];
    }
    float s = g_dinv[gwarp];
    g_h2[gwarp * 32 + lane]   = acc;
    g_agg2[gwarp * 32 + lane] = acc * s * s;
}

// ---------------------------------------------------------------
// 5) edge scatter layer 2: agg2[dst] += norm * h2[src]  (32 wide)
// ---------------------------------------------------------------
__global__ void k_edge2(const int* __restrict__ src, const int* __restrict__ dst, int E) {
    int e = blockIdx.x * blockDim.x + threadIdx.x;
    if (e >= E) return;
    int s = src[e], d = dst[e];
    float nrm = g_dinv[s] * g_dinv[d];
    const float4* hs = (const float4*)&g_h2[s * 32];
    float* ad = &g_agg2[d * 32];
#pragma unroll
    for (int q = 0; q < 8; q++) {
        float4 v = hs[q];
        red_add_v4(ad + q * 4, v.x * nrm, v.y * nrm, v.z * nrm, v.w * nrm);
    }
}

// ---------------------------------------------------------------
// 6) out = log_softmax(relu(agg2 + b2) @ Wc + bc)
// ---------------------------------------------------------------
__global__ void k_out(const float* __restrict__ b2, const float* __restrict__ Wc,
                      const float* __restrict__ bc, float* __restrict__ out) {
    int i = blockIdx.x * blockDim.x + threadIdx.x;
    if (i >= NN) return;

    float z0 = bc[0], z1 = bc[1];
    const float4* row = (const float4*)&g_agg2[i * 32];
#pragma unroll
    for (int q = 0; q < 8; q++) {
        float4 v = row[q];
        float a;
        a = fmaxf(v.x + b2[q * 4 + 0], 0.f); z0 += a * Wc[(q * 4 + 0) * 2]; z1 += a * Wc[(q * 4 + 0) * 2 + 1];
        a = fmaxf(v.y + b2[q * 4 + 1], 0.f); z0 += a * Wc[(q * 4 + 1) * 2]; z1 += a * Wc[(q * 4 + 1) * 2 + 1];
        a = fmaxf(v.z + b2[q * 4 + 2], 0.f); z0 += a * Wc[(q * 4 + 2) * 2]; z1 += a * Wc[(q * 4 + 2) * 2 + 1];
        a = fmaxf(v.w + b2[q * 4 + 3], 0.f); z0 += a * Wc[(q * 4 + 3) * 2]; z1 += a * Wc[(q * 4 + 3) * 2 + 1];
    }
    float m = fmaxf(z0, z1);
    float l = m + logf(expf(z0 - m) + expf(z1 - m));
    out[i * 2 + 0] = z0 - l;
    out[i * 2 + 1] = z1 - l;
}

// ---------------------------------------------------------------
// launch
// ---------------------------------------------------------------
extern "C" void kernel_launch(void* const* d_in, const int* in_sizes, int n_in,
                              void* d_out, int out_size) {
    const float* x  = (const float*)d_in[0];
    const int*   ei = (const int*)  d_in[1];
    const float* W1 = (const float*)d_in[2];
    const float* b1 = (const float*)d_in[3];
    const float* W2 = (const float*)d_in[4];
    const float* b2 = (const float*)d_in[5];
    const float* Wc = (const float*)d_in[6];
    const float* bc = (const float*)d_in[7];
    float* out = (float*)d_out;

    const int E = in_sizes[1] / 2;          // edge_index is [2, E] row-major
    const int* src = ei;
    const int* dst = ei + E;

    const int T = 256;
    const int gN  = (NN + T - 1) / T;
    const int gE  = (E + T - 1) / T;
    const int gW  = (NN * 32 + T - 1) / T;  // warp-per-node kernel

    k_init_deg<<<gN, T>>>();
    k_count   <<<gE, T>>>(dst, E);
    k_dinv    <<<gN, T>>>();
    k_h1      <<<gN, T>>>(x, W1);
    k_edge1   <<<gE, T>>>(src, dst, E);
    k_h2      <<<gW, T>>>(b1, W2);
    k_edge2   <<<gE, T>>>(src, dst, E);
    k_out     <<<gN, T>>>(b2, Wc, bc, out);
}

// round 2
// speedup vs baseline: 2.1371x; 2.1371x over previous
#include <cuda_runtime.h>
#include <math.h>

#define NN   100000
#define EMAX 1600000
#define NB   ((NN + 1023) / 1024)   // 98 scan blocks

// ---- scratch (allocation-free: __device__ globals) ----
__device__ __align__(256) int   g_deg   [NN];
__device__ __align__(256) int   g_cursor[NN];
__device__ __align__(256) float g_dinv  [NN];
__device__ __align__(256) int   g_rowptr[NN + 1];
__device__ __align__(256) int   g_bsum  [128];
__device__ __align__(256) int2  g_csr   [EMAX];     // {src, bitcast(norm)}
__device__ __align__(256) float g_h1    [NN * 64];
__device__ __align__(256) float g_agg1  [NN * 64];
__device__ __align__(256) float g_h2    [NN * 32];

// ---------------------------------------------------------------
// 1) init: deg = 1 (self loop), cursor = 0
// ---------------------------------------------------------------
__global__ void k_init() {
    int i = blockIdx.x * blockDim.x + threadIdx.x;
    if (i < NN) { g_deg[i] = 1; g_cursor[i] = 0; }
}

__global__ void k_count(const int* __restrict__ dst, int E) {
    int e = blockIdx.x * blockDim.x + threadIdx.x;
    if (e < E) atomicAdd(&g_deg[dst[e]], 1);
}

__global__ void k_dinv() {
    int i = blockIdx.x * blockDim.x + threadIdx.x;
    if (i < NN) g_dinv[i] = rsqrtf((float)g_deg[i]);
}

// ---------------------------------------------------------------
// 2) exclusive scan of incoming-edge counts (deg-1) -> row_ptr
// ---------------------------------------------------------------
__global__ void k_scan1() {            // NB blocks x 1024 threads
    int i = blockIdx.x * 1024 + threadIdx.x;
    int v = (i < NN) ? (g_deg[i] - 1) : 0;

    // warp inclusive scan
    int x = v;
#pragma unroll
    for (int o = 1; o < 32; o <<= 1) {
        int y = __shfl_up_sync(0xffffffffu, x, o);
        if ((threadIdx.x & 31) >= o) x += y;
    }
    __shared__ int wsum[32];
    if ((threadIdx.x & 31) == 31) wsum[threadIdx.x >> 5] = x;
    __syncthreads();
    if (threadIdx.x < 32) {
        int w  = wsum[threadIdx.x];
        int xs = w;
#pragma unroll
        for (int o = 1; o < 32; o <<= 1) {
            int y = __shfl_up_sync(0xffffffffu, xs, o);
            if (threadIdx.x >= o) xs += y;
        }
        wsum[threadIdx.x] = xs - w;                 // exclusive warp offsets
        if (threadIdx.x == 31) g_bsum[blockIdx.x] = xs;  // block total
    }
    __syncthreads();
    int excl = x - v + wsum[threadIdx.x >> 5];
    if (i < NN) g_rowptr[i] = excl;
}

__global__ void k_scan2() {            // 1 block, 128 threads
    __shared__ int s[128];
    int v = (threadIdx.x < NB) ? g_bsum[threadIdx.x] : 0;
    s[threadIdx.x] = v;
    __syncthreads();
    for (int o = 1; o < 128; o <<= 1) {
        int y = (threadIdx.x >= (unsigned)o) ? s[threadIdx.x - o] : 0;
        __syncthreads();
        s[threadIdx.x] += y;
        __syncthreads();
    }
    if (threadIdx.x < NB) g_bsum[threadIdx.x] = s[threadIdx.x] - v;  // exclusive
}

__global__ void k_scan3(int E) {
    int i = blockIdx.x * 1024 + threadIdx.x;
    if (i < NN) g_rowptr[i] += g_bsum[blockIdx.x];
    if (i == 0) g_rowptr[NN] = E;
}

// ---------------------------------------------------------------
// 3) fill CSR: for each edge, place (src, norm) in dst's segment
// ---------------------------------------------------------------
__global__ void k_fill(const int* __restrict__ src, const int* __restrict__ dst, int E) {
    int e = blockIdx.x * blockDim.x + threadIdx.x;
    if (e >= E) return;
    int s = src[e], d = dst[e];
    int pos = g_rowptr[d] + atomicAdd(&g_cursor[d], 1);
    float nrm = g_dinv[s] * g_dinv[d];
    g_csr[pos] = make_int2(s, __float_as_int(nrm));
}

// ---------------------------------------------------------------
// 4) h1 = x @ W1  (N x 7 @ 7 x 64) with shared-tiled x
// ---------------------------------------------------------------
__global__ void k_h1(const float* __restrict__ x, const float* __restrict__ W1) {
    __shared__ float W[7 * 64];
    __shared__ float xs[256 * 7];
    int t = threadIdx.x;
    for (int j = t; j < 7 * 64; j += 256) W[j] = W1[j];
    int base = blockIdx.x * 256;
    for (int j = t; j < 256 * 7; j += 256) {
        int g = base * 7 + j;
        xs[j] = (g < NN * 7) ? x[g] : 0.f;
    }
    __syncthreads();

    int i = base + t;
    if (i >= NN) return;

    float xi[7];
#pragma unroll
    for (int k = 0; k < 7; k++) xi[k] = xs[t * 7 + k];

#pragma unroll 4
    for (int c4 = 0; c4 < 16; c4++) {
        float a0 = 0.f, a1 = 0.f, a2 = 0.f, a3 = 0.f;
#pragma unroll
        for (int k = 0; k < 7; k++) {
            const float* wr = &W[k * 64 + c4 * 4];
            a0 += xi[k] * wr[0];
            a1 += xi[k] * wr[1];
            a2 += xi[k] * wr[2];
            a3 += xi[k] * wr[3];
        }
        *(float4*)&g_h1[i * 64 + c4 * 4] = make_float4(a0, a1, a2, a3);
    }
}

// ---------------------------------------------------------------
// 5) gather layer 1: agg1[i] = dinv^2*h1[i] + sum_e norm*h1[src]
//    one warp per node, lane holds features (2*lane, 2*lane+1)
// ---------------------------------------------------------------
__global__ void k_gather1() {
    int gwarp = (blockIdx.x * blockDim.x + threadIdx.x) >> 5;
    int lane  = threadIdx.x & 31;
    if (gwarp >= NN) return;

    int beg = g_rowptr[gwarp], end = g_rowptr[gwarp + 1];
    float s  = g_dinv[gwarp];
    float ss = s * s;

    float2 h = *(const float2*)&g_h1[gwarp * 64 + 2 * lane];
    float ax = h.x * ss, ay = h.y * ss;

    int p = beg;
    for (; p + 2 <= end; p += 2) {
        int2 e0 = g_csr[p];
        int2 e1 = g_csr[p + 1];
        float2 v0 = *(const float2*)&g_h1[e0.x * 64 + 2 * lane];
        float2 v1 = *(const float2*)&g_h1[e1.x * 64 + 2 * lane];
        float n0 = __int_as_float(e0.y), n1 = __int_as_float(e1.y);
        ax += v0.x * n0 + v1.x * n1;
        ay += v0.y * n0 + v1.y * n1;
    }
    if (p < end) {
        int2 e0 = g_csr[p];
        float2 v0 = *(const float2*)&g_h1[e0.x * 64 + 2 * lane];
        float n0 = __int_as_float(e0.y);
        ax += v0.x * n0;
        ay += v0.y * n0;
    }
    *(float2*)&g_agg1[gwarp * 64 + 2 * lane] = make_float2(ax, ay);
}

// ---------------------------------------------------------------
// 6) h2 = relu(agg1 + b1) @ W2   (64 -> 32), warp per node
// ---------------------------------------------------------------
__global__ void k_h2(const float* __restrict__ b1, const float* __restrict__ W2) {
    __shared__ float W[64 * 32];
    __shared__ float b[64];
    for (int t = threadIdx.x; t < 64 * 32; t += blockDim.x) W[t] = W2[t];
    if (threadIdx.x < 64) b[threadIdx.x] = b1[threadIdx.x];
    __syncthreads();

    int gwarp = (blockIdx.x * blockDim.x + threadIdx.x) >> 5;
    int lane  = threadIdx.x & 31;
    if (gwarp >= NN) return;

    const float* row = &g_agg1[gwarp * 64];
    float acc = 0.f;
#pragma unroll
    for (int k = 0; k < 64; k++) {
        float a = fmaxf(row[k] + b[k], 0.f);   // uniform load -> broadcast
        acc += a * W[k * 32 + lane];
    }
    g_h2[gwarp * 32 + lane] = acc;
}

// ---------------------------------------------------------------
// 7) gather layer 2 + fused classifier + log_softmax
//    one warp per node, lane = feature
// ---------------------------------------------------------------
__global__ void k_gather2(const float* __restrict__ b2, const float* __restrict__ Wc,
                          const float* __restrict__ bc, float* __restrict__ out) {
    int gwarp = (blockIdx.x * blockDim.x + threadIdx.x) >> 5;
    int lane  = threadIdx.x & 31;
    if (gwarp >= NN) return;

    int beg = g_rowptr[gwarp], end = g_rowptr[gwarp + 1];
    float s  = g_dinv[gwarp];
    float ss = s * s;

    float acc = g_h2[gwarp * 32 + lane] * ss;

    int p = beg;
    for (; p + 2 <= end; p += 2) {
        int2 e0 = g_csr[p];
        int2 e1 = g_csr[p + 1];
        float v0 = g_h2[e0.x * 32 + lane];
        float v1 = g_h2[e1.x * 32 + lane];
        acc += v0 * __int_as_float(e0.y) + v1 * __int_as_float(e1.y);
    }
    if (p < end) {
        int2 e0 = g_csr[p];
        acc += g_h2[e0.x * 32 + lane] * __int_as_float(e0.y);
    }

    // classifier: a = relu(acc + b2[lane]); z = a @ Wc + bc
    float a  = fmaxf(acc + b2[lane], 0.f);
    float z0 = a * Wc[lane * 2 + 0];
    float z1 = a * Wc[lane * 2 + 1];
#pragma unroll
    for (int o = 16; o > 0; o >>= 1) {
        z0 += __shfl_xor_sync(0xffffffffu, z0, o);
        z1 += __shfl_xor_sync(0xffffffffu, z1, o);
    }
    if (lane == 0) {
        z0 += bc[0]; z1 += bc[1];
        float m = fmaxf(z0, z1);
        float l = m + logf(expf(z0 - m) + expf(z1 - m));
        *(float2*)&out[gwarp * 2] = make_float2(z0 - l, z1 - l);
    }
}

// ---------------------------------------------------------------
// launch
// ---------------------------------------------------------------
extern "C" void kernel_launch(void* const* d_in, const int* in_sizes, int n_in,
                              void* d_out, int out_size) {
    const float* x  = (const float*)d_in[0];
    const int*   ei = (const int*)  d_in[1];
    const float* W1 = (const float*)d_in[2];
    const float* b1 = (const float*)d_in[3];
    const float* W2 = (const float*)d_in[4];
    const float* b2 = (const float*)d_in[5];
    const float* Wc = (const float*)d_in[6];
    const float* bc = (const float*)d_in[7];
    float* out = (float*)d_out;

    const int E = in_sizes[1] / 2;
    const int* src = ei;
    const int* dst = ei + E;

    const int T  = 256;
    const int gN = (NN + T - 1) / T;
    const int gE = (E + T - 1) / T;
    const int gW = (NN * 32 + T - 1) / T;   // warp-per-node kernels

    k_init  <<<(NN + 1023) / 1024, 1024>>>();
    k_count <<<gE, T>>>(dst, E);
    k_dinv  <<<gN, T>>>();
    k_scan1 <<<NB, 1024>>>();
    k_scan2 <<<1, 128>>>();
    k_scan3 <<<NB, 1024>>>(E);
    k_fill  <<<gE, T>>>(src, dst, E);
    k_h1    <<<gN, T>>>(x, W1);
    k_gather1<<<gW, T>>>();
    k_h2    <<<gW, T>>>(b1, W2);
    k_gather2<<<gW, T>>>(b2, Wc, bc, out);
}